// round 1
// baseline (speedup 1.0000x reference)
#include <cuda_runtime.h>

// Problem constants (fixed shapes for this problem instance)
#define B_  4
#define T_  512
#define G_  129
#define F_  96
#define O_  96
#define KK  3

#define TT  128          // T-tile per CTA
#define TM  4            // t-rows per thread
#define TOPAIR 6         // 12 o-cols per thread as 6 f32x2 pairs

#define XS_STRIDE 97     // padded row stride (bank-conflict-free A loads)
#define XS_ROWS  (TT + 2)
#define WS_FLOATS (KK * F_ * O_)            // 27648 floats = 108 KB
#define XS_FLOATS (XS_ROWS * XS_STRIDE)     // 12610 floats ~ 49.3 KB
#define SMEM_BYTES ((WS_FLOATS + XS_FLOATS) * 4)

__device__ __forceinline__ unsigned long long pack_dup(float a) {
    unsigned long long r;
    asm("mov.b64 %0, {%1, %1};" : "=l"(r) : "f"(a));
    return r;
}
__device__ __forceinline__ unsigned long long pack2(float a, float b) {
    unsigned long long r;
    asm("mov.b64 %0, {%1, %2};" : "=l"(r) : "f"(a), "f"(b));
    return r;
}
// Packed dual-FMA: d.lo = a.lo*b.lo + d.lo ; d.hi = a.hi*b.hi + d.hi
__device__ __forceinline__ void fma2(unsigned long long& d, unsigned long long a, unsigned long long b) {
    asm("fma.rn.f32x2 %0, %1, %2, %0;" : "+l"(d) : "l"(a), "l"(b));
}
__device__ __forceinline__ float2 unpack2(unsigned long long v) {
    float2 r;
    asm("mov.b64 {%0, %1}, %2;" : "=f"(r.x), "=f"(r.y) : "l"(v));
    return r;
}

__global__ __launch_bounds__(256, 1)
void conv1dgroup_kernel(const float* __restrict__ x,
                        const float* __restrict__ w,
                        const float* __restrict__ bias,
                        float* __restrict__ out)
{
    extern __shared__ float sm[];
    float* ws = sm;                    // [KK][F_][O_]
    float* xs = sm + WS_FLOATS;        // [XS_ROWS][XS_STRIDE]

    const int tid = threadIdx.x;
    const int g  = blockIdx.y;
    const int b  = blockIdx.x >> 2;            // T_/TT = 4 tiles per batch
    const int tb = (blockIdx.x & 3) * TT;

    // ---- Load weight[g] (O,F,K source order, coalesced float4) -> smem [K][F][O]
    {
        const float4* wg4 = (const float4*)(w + (size_t)g * WS_FLOATS);
        for (int q = tid; q < WS_FLOATS / 4; q += 256) {
            float4 v = wg4[q];
            int e = q * 4;                 // element index: o*288 + f*3 + k
            int o = e / (F_ * KK);
            int r = e - o * (F_ * KK);     // f*3 + k ; 288 % 4 == 0 so o constant over 4 elems
            const float* vf = (const float*)&v;
            #pragma unroll
            for (int j = 0; j < 4; ++j) {
                int rr = r + j;
                int f = rr / KK;
                int k = rr - KK * f;
                ws[(k * F_ + f) * O_ + o] = vf[j];
            }
        }
    }

    // ---- Load x tile with +/-1 halo (zero-padded at batch-local T boundaries)
    {
        const float* xbase = x + (((size_t)b * T_) * G_ + g) * F_;
        for (int q = tid; q < XS_ROWS * (F_ / 4); q += 256) {
            int rrow = q / (F_ / 4);
            int c4   = q - rrow * (F_ / 4);
            int gt   = tb + rrow - 1;
            float4 v = make_float4(0.f, 0.f, 0.f, 0.f);
            if (gt >= 0 && gt < T_)
                v = *(const float4*)(xbase + (size_t)gt * (G_ * F_) + c4 * 4);
            float* dst = xs + rrow * XS_STRIDE + c4 * 4;
            dst[0] = v.x; dst[1] = v.y; dst[2] = v.z; dst[3] = v.w;
        }
    }

    __syncthreads();

    const int tx  = tid & 7;    // o-block: o = tx*12 .. tx*12+11
    const int ty  = tid >> 3;   // t-block: rows ty*4 .. ty*4+3
    const int ty4 = ty * TM;

    unsigned long long acc[TM][TOPAIR];
    {
        const float* bg = bias + g * O_ + tx * 12;
        #pragma unroll
        for (int j = 0; j < TOPAIR; ++j) {
            unsigned long long bv = pack2(bg[2 * j], bg[2 * j + 1]);
            #pragma unroll
            for (int i = 0; i < TM; ++i) acc[i][j] = bv;
        }
    }

    // ---- Main loop: out[t,o] += x[t+k-1, f] * w[k,f,o]
    #pragma unroll
    for (int k = 0; k < KK; ++k) {
        const float* wsk = ws + k * (F_ * O_) + tx * 12;
        const float* xsk = xs + (ty4 + k) * XS_STRIDE;
        #pragma unroll 4
        for (int f = 0; f < F_; ++f) {
            unsigned long long bfr[TOPAIR];
            const ulonglong2* bp = (const ulonglong2*)(wsk + f * O_);
            ulonglong2 u0 = bp[0], u1 = bp[1], u2 = bp[2];
            bfr[0] = u0.x; bfr[1] = u0.y;
            bfr[2] = u1.x; bfr[3] = u1.y;
            bfr[4] = u2.x; bfr[5] = u2.y;
            #pragma unroll
            for (int i = 0; i < TM; ++i) {
                unsigned long long a2 = pack_dup(xsk[i * XS_STRIDE + f]);
                #pragma unroll
                for (int j = 0; j < TOPAIR; ++j) fma2(acc[i][j], a2, bfr[j]);
            }
        }
    }

    // ---- Store (coalesced float4 along contiguous O)
    #pragma unroll
    for (int i = 0; i < TM; ++i) {
        int t = tb + ty4 + i;
        float* op = out + ((((size_t)b * T_ + t) * G_ + g) * O_) + tx * 12;
        #pragma unroll
        for (int j = 0; j < 3; ++j) {
            float2 lo = unpack2(acc[i][2 * j]);
            float2 hi = unpack2(acc[i][2 * j + 1]);
            *(float4*)(op + j * 4) = make_float4(lo.x, lo.y, hi.x, hi.y);
        }
    }
}

extern "C" void kernel_launch(void* const* d_in, const int* in_sizes, int n_in,
                              void* d_out, int out_size)
{
    const float* x    = (const float*)d_in[0];
    const float* wgt  = (const float*)d_in[1];
    const float* bias = (const float*)d_in[2];
    float* out        = (float*)d_out;

    cudaFuncSetAttribute(conv1dgroup_kernel,
                         cudaFuncAttributeMaxDynamicSharedMemorySize, SMEM_BYTES);

    dim3 grid((T_ / TT) * B_, G_);   // 16 x 129 = 2064 CTAs
    conv1dgroup_kernel<<<grid, 256, SMEM_BYTES>>>(x, wgt, bias, out);
}

// round 3
// speedup vs baseline: 1.5274x; 1.5274x over previous
#include <cuda_runtime.h>

// Problem constants (fixed shapes)
#define B_  4
#define T_  512
#define G_  129
#define F_  96
#define O_  96
#define KK  3

#define TT  256          // T-tile per CTA
#define TM  8            // t-rows per thread
#define TOPAIR 6         // 12 o-cols per thread as 6 f32x2 pairs

#define XS_STRIDE 100    // padded row stride, multiple of 4 (aligned LDS.128)
#define XS_ROWS  (TT + 2)
#define WS_FLOATS (KK * F_ * O_)            // 27648 floats = 108 KB
#define XS_FLOATS (XS_ROWS * XS_STRIDE)     // 25800 floats ~ 103.2 KB
#define SMEM_BYTES ((WS_FLOATS + XS_FLOATS) * 4)   // 213,792 B

__device__ __forceinline__ unsigned long long pack_dup(float a) {
    unsigned long long r;
    asm("mov.b64 %0, {%1, %1};" : "=l"(r) : "f"(a));
    return r;
}
__device__ __forceinline__ unsigned long long pack2(float a, float b) {
    unsigned long long r;
    asm("mov.b64 %0, {%1, %2};" : "=l"(r) : "f"(a), "f"(b));
    return r;
}
// Packed dual-FMA: d.lo += a.lo*b.lo ; d.hi += a.hi*b.hi
__device__ __forceinline__ void fma2(unsigned long long& d, unsigned long long a, unsigned long long b) {
    asm("fma.rn.f32x2 %0, %1, %2, %0;" : "+l"(d) : "l"(a), "l"(b));
}
__device__ __forceinline__ float2 unpack2(unsigned long long v) {
    float2 r;
    asm("mov.b64 {%0, %1}, %2;" : "=f"(r.x), "=f"(r.y) : "l"(v));
    return r;
}

__global__ __launch_bounds__(256, 1)
void conv1dgroup_kernel(const float* __restrict__ x,
                        const float* __restrict__ w,
                        const float* __restrict__ bias,
                        float* __restrict__ out)
{
    extern __shared__ float sm[];
    float* ws = sm;                    // [KK][F_][O_]
    float* xs = sm + WS_FLOATS;        // [XS_ROWS][XS_STRIDE]

    const int tid = threadIdx.x;
    const int g  = blockIdx.y;
    const int b  = blockIdx.x >> 1;            // T_/TT = 2 tiles per batch
    const int tb = (blockIdx.x & 1) * TT;

    // ---- Load weight[g] (src order o*288+f*3+k, coalesced float4) -> smem [K][F][O]
    {
        const float4* wg4 = (const float4*)(w + (size_t)g * WS_FLOATS);
        for (int q = tid; q < WS_FLOATS / 4; q += 256) {
            float4 v = wg4[q];
            int e = q * 4;
            int o = e / (F_ * KK);
            int r = e - o * (F_ * KK);     // 288 % 4 == 0 -> o constant over the 4 elems
            const float* vf = (const float*)&v;
            #pragma unroll
            for (int j = 0; j < 4; ++j) {
                int rr = r + j;
                int f = rr / KK;
                int k = rr - KK * f;
                ws[(k * F_ + f) * O_ + o] = vf[j];
            }
        }
    }

    // ---- Load x tile with +/-1 halo (zero-padded at batch T boundaries)
    {
        const float* xbase = x + (((size_t)b * T_) * G_ + g) * F_;
        for (int q = tid; q < XS_ROWS * (F_ / 4); q += 256) {
            int rrow = q / (F_ / 4);
            int c4   = q - rrow * (F_ / 4);
            int gt   = tb + rrow - 1;
            float4 v = make_float4(0.f, 0.f, 0.f, 0.f);
            if (gt >= 0 && gt < T_)
                v = *(const float4*)(xbase + (size_t)gt * (G_ * F_) + c4 * 4);
            *(float4*)(xs + rrow * XS_STRIDE + c4 * 4) = v;
        }
    }

    __syncthreads();

    const int tx  = tid & 7;    // o-block: o = tx*12 .. tx*12+11
    const int ty8 = (tid >> 3) * TM;   // t-rows ty8 .. ty8+7 within tile

    unsigned long long acc[TM][TOPAIR];
    {
        const float* bg = bias + g * O_ + tx * 12;
        #pragma unroll
        for (int j = 0; j < TOPAIR; ++j) {
            unsigned long long bv = pack2(bg[2 * j], bg[2 * j + 1]);
            #pragma unroll
            for (int i = 0; i < TM; ++i) acc[i][j] = bv;
        }
    }

    const float* xrow = xs + ty8 * XS_STRIDE;
    const float* wso  = ws + tx * 12;

    // ---- Main loop over f in chunks of 4
    #pragma unroll 1
    for (int f4 = 0; f4 < F_ / 4; ++f4) {
        // 10 rows cover i=0..7 plus k-halo of 2
        float4 xr[TM + 2];
        #pragma unroll
        for (int r = 0; r < TM + 2; ++r)
            xr[r] = *(const float4*)(xrow + r * XS_STRIDE + f4 * 4);

        #pragma unroll
        for (int fj = 0; fj < 4; ++fj) {
            unsigned long long xd[TM + 2];
            #pragma unroll
            for (int r = 0; r < TM + 2; ++r)
                xd[r] = pack_dup(((const float*)&xr[r])[fj]);

            #pragma unroll
            for (int k = 0; k < KK; ++k) {
                const float* wp = wso + (k * F_ + f4 * 4 + fj) * O_;
                ulonglong2 u0 = *(const ulonglong2*)(wp);
                ulonglong2 u1 = *(const ulonglong2*)(wp + 4);
                ulonglong2 u2 = *(const ulonglong2*)(wp + 8);
                unsigned long long bfr[TOPAIR];
                bfr[0] = u0.x; bfr[1] = u0.y;
                bfr[2] = u1.x; bfr[3] = u1.y;
                bfr[4] = u2.x; bfr[5] = u2.y;
                #pragma unroll
                for (int i = 0; i < TM; ++i) {
                    #pragma unroll
                    for (int j = 0; j < TOPAIR; ++j)
                        fma2(acc[i][j], xd[i + k], bfr[j]);
                }
            }
        }
    }

    // ---- Store (coalesced float4 along contiguous O)
    #pragma unroll
    for (int i = 0; i < TM; ++i) {
        int t = tb + ty8 + i;
        float* op = out + ((((size_t)b * T_ + t) * G_ + g) * O_) + tx * 12;
        #pragma unroll
        for (int j = 0; j < 3; ++j) {
            float2 lo = unpack2(acc[i][2 * j]);
            float2 hi = unpack2(acc[i][2 * j + 1]);
            *(float4*)(op + j * 4) = make_float4(lo.x, lo.y, hi.x, hi.y);
        }
    }
}

extern "C" void kernel_launch(void* const* d_in, const int* in_sizes, int n_in,
                              void* d_out, int out_size)
{
    const float* x    = (const float*)d_in[0];
    const float* wgt  = (const float*)d_in[1];
    const float* bias = (const float*)d_in[2];
    float* out        = (float*)d_out;

    cudaFuncSetAttribute(conv1dgroup_kernel,
                         cudaFuncAttributeMaxDynamicSharedMemorySize, SMEM_BYTES);

    dim3 grid((T_ / TT) * B_, G_);   // 8 x 129 = 1032 CTAs
    conv1dgroup_kernel<<<grid, 256, SMEM_BYTES>>>(x, wgt, bias, out);
}

// round 5
// speedup vs baseline: 2.8565x; 1.8702x over previous
#include <cuda_runtime.h>
#include <cstdint>

#define B_  4
#define T_  512
#define G_  129
#define F_  96
#define O_  96

#define MT      256
#define XROWS   (MT + 2)
#define XSTRIDE 100                       // A-frag bank-conflict-free (100 mod 32 = 4)
#define XS_FLOATS (XROWS * XSTRIDE)       // 25800

#define KROW_STRIDE  104                  // B-frag bank-conflict-free (104 mod 32 = 8)
#define KSTEP_STRIDE (4 * KROW_STRIDE)    // 416
#define KK_STRIDE    (12 * KSTEP_STRIDE)  // 4992
#define PLANE_STRIDE (3 * KK_STRIDE)      // 14976 (plane0: k, plane1: k+4)
#define WS_FLOATS    (2 * PLANE_STRIDE)   // 29952

#define SMEM_BYTES ((WS_FLOATS + XS_FLOATS) * 4)   // 223,008 B

__device__ __forceinline__ float f2tf32f(float f) {
    uint32_t r;
    asm("cvt.rna.tf32.f32 %0, %1;" : "=r"(r) : "f"(f));
    return __uint_as_float(r);
}

__device__ __forceinline__ void mma_tf32(float c[4], uint32_t a0, uint32_t a1,
                                         uint32_t a2, uint32_t a3,
                                         uint32_t b0, uint32_t b1) {
    asm volatile(
        "mma.sync.aligned.m16n8k8.row.col.f32.tf32.tf32.f32 "
        "{%0,%1,%2,%3}, {%4,%5,%6,%7}, {%8,%9}, {%0,%1,%2,%3};"
        : "+f"(c[0]), "+f"(c[1]), "+f"(c[2]), "+f"(c[3])
        : "r"(a0), "r"(a1), "r"(a2), "r"(a3), "r"(b0), "r"(b1));
}

__global__ __launch_bounds__(256, 1)
void conv1d_mma_kernel(const float* __restrict__ x,
                       const float* __restrict__ w,
                       const float* __restrict__ bias,
                       float* __restrict__ out)
{
    extern __shared__ float sm[];
    float* ws = sm;                    // [plane2][kk3][kstep12][krow4][104]
    float* xs = sm + WS_FLOATS;        // [XROWS][XSTRIDE]

    const int tid = threadIdx.x, wid = tid >> 5, lane = tid & 31;
    const int g    = blockIdx.y;
    const int m0   = blockIdx.x * MT;          // global flattened (b,t) row
    const int b    = m0 >> 9;
    const int tl0  = m0 & 511;

    // ---- W[g] -> smem (tf32, two k-planes, conflict-free B layout)
    {
        const float4* wg4 = (const float4*)(w + (size_t)g * (O_ * F_ * 3));
        for (int q = tid; q < (O_ * F_ * 3) / 4; q += 256) {
            float4 v = wg4[q];
            int e = q * 4;
            int o = e / (F_ * 3);
            int rem = e - o * (F_ * 3);        // 288 % 4 == 0 -> o fixed over the 4
            const float* vf = (const float*)&v;
            #pragma unroll
            for (int j = 0; j < 4; ++j) {
                int rr = rem + j;
                int f = rr / 3, kk = rr - 3 * f;
                int kstep = f >> 3, krow = f & 3, plane = (f >> 2) & 1;
                ws[plane * PLANE_STRIDE + kk * KK_STRIDE + kstep * KSTEP_STRIDE
                   + krow * KROW_STRIDE + o] = f2tf32f(vf[j]);
            }
        }
    }

    // ---- x tile (+/-1 halo, zero-padded at batch T edges) -> smem tf32
    {
        const float* xg = x + (((size_t)b * T_) * G_ + g) * F_;
        for (int q = tid; q < XROWS * (F_ / 4); q += 256) {
            int p = q / (F_ / 4), c4 = q - p * (F_ / 4);
            int t = tl0 - 1 + p;
            float4 v = make_float4(0.f, 0.f, 0.f, 0.f);
            if (t >= 0 && t < T_) v = *(const float4*)(xg + (size_t)t * (G_ * F_) + c4 * 4);
            v.x = f2tf32f(v.x); v.y = f2tf32f(v.y);
            v.z = f2tf32f(v.z); v.w = f2tf32f(v.w);
            *(float4*)(xs + p * XSTRIDE + c4 * 4) = v;
        }
    }
    __syncthreads();

    // ---- accumulators pre-loaded with bias (C frag cols: 2*(lane&3), +1)
    float acc[2][12][4];
    {
        const float* bg = bias + g * O_ + 2 * (lane & 3);
        #pragma unroll
        for (int n = 0; n < 12; ++n) {
            float b0 = bg[n * 8], b1 = bg[n * 8 + 1];
            #pragma unroll
            for (int mb = 0; mb < 2; ++mb) {
                acc[mb][n][0] = b0; acc[mb][n][1] = b1;
                acc[mb][n][2] = b0; acc[mb][n][3] = b1;
            }
        }
    }

    // ---- main loop: 3 conv shifts x 12 K8-steps, warp tile m32 x n96
    const float* pa_base = xs + (wid * 32 + (lane >> 2)) * XSTRIDE + (lane & 3);
    const float* pb_base = ws + (lane & 3) * KROW_STRIDE + (lane >> 2);

    #pragma unroll
    for (int kk = 0; kk < 3; ++kk) {
        const float* pak = pa_base + kk * XSTRIDE;
        const float* pbk = pb_base + kk * KK_STRIDE;
        #pragma unroll 4
        for (int ks = 0; ks < 12; ++ks) {
            const float* pa = pak + ks * 8;
            const float* pb = pbk + ks * KSTEP_STRIDE;
            // A fragments: rows (lane>>2)+{0,8,16,24}, cols (lane&3)+{0,4}
            uint32_t a00 = __float_as_uint(pa[0]);
            uint32_t a01 = __float_as_uint(pa[8 * XSTRIDE]);
            uint32_t a02 = __float_as_uint(pa[4]);
            uint32_t a03 = __float_as_uint(pa[8 * XSTRIDE + 4]);
            uint32_t a10 = __float_as_uint(pa[16 * XSTRIDE]);
            uint32_t a11 = __float_as_uint(pa[24 * XSTRIDE]);
            uint32_t a12 = __float_as_uint(pa[16 * XSTRIDE + 4]);
            uint32_t a13 = __float_as_uint(pa[24 * XSTRIDE + 4]);
            #pragma unroll
            for (int n = 0; n < 12; ++n) {
                uint32_t b0 = __float_as_uint(pb[n * 8]);
                uint32_t b1 = __float_as_uint(pb[PLANE_STRIDE + n * 8]);
                mma_tf32(acc[0][n], a00, a01, a02, a03, b0, b1);
                mma_tf32(acc[1][n], a10, a11, a12, a13, b0, b1);
            }
        }
    }

    // ---- store: C frag rows (lane>>2)+{0,8}, cols 2*(lane&3) (+1) per n-block
    const int colb = 2 * (lane & 3);
    #pragma unroll
    for (int mb = 0; mb < 2; ++mb) {
        int rbase = m0 + wid * 32 + mb * 16 + (lane >> 2);
        #pragma unroll
        for (int h = 0; h < 2; ++h) {
            size_t gm = (size_t)(rbase + h * 8);
            float* op = out + (gm * G_ + g) * O_ + colb;
            #pragma unroll
            for (int n = 0; n < 12; ++n)
                *(float2*)(op + n * 8) = make_float2(acc[mb][n][2 * h], acc[mb][n][2 * h + 1]);
        }
    }
}

extern "C" void kernel_launch(void* const* d_in, const int* in_sizes, int n_in,
                              void* d_out, int out_size)
{
    const float* x    = (const float*)d_in[0];
    const float* wgt  = (const float*)d_in[1];
    const float* bias = (const float*)d_in[2];
    float* out        = (float*)d_out;

    cudaFuncSetAttribute(conv1d_mma_kernel,
                         cudaFuncAttributeMaxDynamicSharedMemorySize, SMEM_BYTES);

    dim3 grid((B_ * T_) / MT, G_);   // 8 x 129 = 1032 CTAs
    conv1d_mma_kernel<<<grid, 256, SMEM_BYTES>>>(x, wgt, bias, out);
}